// round 6
// baseline (speedup 1.0000x reference)
#include <cuda_runtime.h>

#define DECAYF 0.951229424500714f   // exp(-1/20)

// Persistent state (no allocs allowed)
__device__ float         g_vm0[2097152];      // [16 b][32 o][64][64]
__device__ unsigned char g_s0b[2097152];
__device__ float         g_vm1[4194304];      // [16 b][64 o][64][64]
__device__ float         g_flatT[1048576];    // pooled spikes [i=65536][b=16]
__device__ float         g_part[524288];      // dense0 partials [is=64][j=512][b=16]
__device__ float         g_vm2[8192], g_s2f[8192];   // [b][j]
__device__ float         g_vm3[176],  g_acc[176];
__device__ float         g_nop[32];

// ---- packed f32x2 helpers ----
__device__ __forceinline__ unsigned long long pack2(float a, float b) {
    unsigned long long r;
    asm("mov.b64 %0, {%1, %2};" : "=l"(r)
        : "r"(__float_as_uint(a)), "r"(__float_as_uint(b)));
    return r;
}
__device__ __forceinline__ void unpack2(unsigned long long v, float& a, float& b) {
    unsigned lo, hi;
    asm("mov.b64 {%0, %1}, %2;" : "=r"(lo), "=r"(hi) : "l"(v));
    a = __uint_as_float(lo); b = __uint_as_float(hi);
}
#define FMA2(acc, w, s) asm("fma.rn.f32x2 %0, %1, %2, %0;" : "+l"(acc) : "l"(w), "l"(s))
#define ADD2(acc, v)    asm("add.rn.f32x2 %0, %0, %1;"      : "+l"(acc) : "l"(v))

// dummy kernel: aligns the ncu-captured launch (#3) onto k_dense0(t=0)
__global__ void k_nop() { g_nop[threadIdx.x] = 0.f; }

// ---------------------------------------------------------------------------
// conv0 (2->32, 3x3 pad1) + LIF0.  grid = 16 b * 32 o = 512 blocks, 256 thr.
// Spikes stored as bytes; LIF gate recomputed from vm0.
// ---------------------------------------------------------------------------
__global__ void __launch_bounds__(256) k_conv0(const float* __restrict__ in,
                                               const float* __restrict__ W0, int t)
{
    int bid = blockIdx.x;
    int o = bid & 31, b = bid >> 5;
    float w[18];
#pragma unroll
    for (int i = 0; i < 18; i++) w[i] = W0[o * 18 + i];
    const float* x0 = in + (((long)(b * 16 + t)) << 13);

#pragma unroll 4
    for (int p = threadIdx.x; p < 4096; p += 256) {
        int y = p >> 6, x = p & 63;
        float acc = 0.f;
#pragma unroll
        for (int c = 0; c < 2; c++)
#pragma unroll
            for (int ky = 0; ky < 3; ky++) {
                int yy = y + ky - 1;
                if ((unsigned)yy < 64u)
#pragma unroll
                    for (int kx = 0; kx < 3; kx++) {
                        int xx = x + kx - 1;
                        if ((unsigned)xx < 64u) {
                            float v = x0[(c << 12) + (yy << 6) + xx];
                            v = fminf(fmaxf(v, 0.f), 1.f);
                            acc = fmaf(w[c * 9 + ky * 3 + kx], v, acc);
                        }
                    }
            }
        long idx = (((long)bid) << 12) + p;
        float vm;
        if (t) {
            float vp = g_vm0[idx];
            vm = vp * (vp > 0.5f ? 0.f : DECAYF) + acc;
        } else vm = acc;
        g_vm0[idx] = vm;
        g_s0b[idx] = vm > 0.5f ? (unsigned char)1 : (unsigned char)0;
    }
}

// ---------------------------------------------------------------------------
// conv1 (32->64, 3x3) + LIF1 + fused 2x2 maxpool (binary OR) -> g_flatT.
// grid = 16 b * 16 tiles(16x16) * 2 och-halves = 512 blocks, 256 threads.
// Thread: 4 och-pairs x 4 px = 16 f32x2 accumulators.
// smem: paired weights 32 och (36864B) + u8 halo [32][18][20] (11520B)
//   = 48384B -> 3 blocks/SM;  __launch_bounds__(256,3) (<=85 regs) gives
//   ptxas headroom to hoist/prefetch the weight LDS.128s across FMA bursts.
// ---------------------------------------------------------------------------
__global__ void __launch_bounds__(256, 3) k_conv1(const float* __restrict__ W1, int t)
{
    extern __shared__ unsigned char sh1[];
    unsigned long long* wsm = (unsigned long long*)sh1;   // [ck=288][pair=16]
    unsigned char* ssm = sh1 + 36864;                     // [c=32][18][20]

    int bid  = blockIdx.x;
    int oh   = bid & 1;
    int tile = (bid >> 1) & 15;
    int b    = bid >> 5;
    int ty0  = (tile >> 2) << 4, tx0 = (tile & 3) << 4;
    int tid  = threadIdx.x;
    int pg   = tid >> 6;          // 0..3 : pair group (4 pairs = 8 och)
    int pxg  = tid & 63;
    int row  = pxg & 15;
    int px0  = (pxg >> 4) << 2;   // 0,4,8,12

    // weights: pair (o, o+1), o = oh*32 + 2*pr
    for (int idx = tid; idx < 4608; idx += 256) {
        int ck = idx >> 4, pr = idx & 15;
        const float* wb = W1 + (oh * 32 + 2 * pr) * 288 + ck;
        wsm[ck * 16 + pr] = pack2(wb[0], wb[288]);
    }
    // u8 spike halo (zero padded), rows padded to 20 bytes
    for (int idx = tid; idx < 11520; idx += 256) {
        int c = idx / 360, r = idx - c * 360;
        int yy = r / 20, xx = r - yy * 20;
        int y = ty0 - 1 + yy, x = tx0 - 1 + xx;
        unsigned char v = 0;
        if (xx < 18 && (unsigned)y < 64u && (unsigned)x < 64u)
            v = g_s0b[(((b << 5) + c) << 12) + (y << 6) + x];
        ssm[idx] = v;
    }
    __syncthreads();

    unsigned long long acc[16];
#pragma unroll
    for (int i = 0; i < 16; i++) acc[i] = 0ull;

    for (int c = 0; c < 32; ++c) {
#pragma unroll
        for (int ky = 0; ky < 3; ++ky) {
            const unsigned char* rp = ssm + c * 360 + (row + ky) * 20 + px0;
            unsigned v0 = *(const unsigned*)rp;         // bytes 0..3
            unsigned v1 = *(const unsigned*)(rp + 4);   // bytes 4..7 (use 0,1)
            unsigned long long s2[6];
            {
                float f0 = (float)( v0        & 0xffu);
                float f1 = (float)((v0 >>  8) & 0xffu);
                float f2 = (float)((v0 >> 16) & 0xffu);
                float f3 = (float)( v0 >> 24        );
                float f4 = (float)( v1        & 0xffu);
                float f5 = (float)((v1 >>  8) & 0xffu);
                s2[0] = pack2(f0, f0); s2[1] = pack2(f1, f1);
                s2[2] = pack2(f2, f2); s2[3] = pack2(f3, f3);
                s2[4] = pack2(f4, f4); s2[5] = pack2(f5, f5);
            }
#pragma unroll
            for (int kx = 0; kx < 3; ++kx) {
                const ulonglong2* wp =
                    (const ulonglong2*)(wsm + (c * 9 + ky * 3 + kx) * 16 + (pg << 2));
                ulonglong2 wa = wp[0], wb = wp[1];
                unsigned long long wv[4] = {wa.x, wa.y, wb.x, wb.y};
#pragma unroll
                for (int g = 0; g < 4; ++g)
#pragma unroll
                    for (int px = 0; px < 4; ++px)
                        FMA2(acc[g * 4 + px], wv[g], s2[kx + px]);
            }
        }
    }

    // LIF1 + pooled bits.  bit index = ol*2 + xp  (ol = channel 0..7).
    int y = ty0 + row, x = tx0 + px0;
    unsigned pool = 0u;
#pragma unroll
    for (int g = 0; g < 4; ++g) {
        int o0 = oh * 32 + (pg << 3) + 2 * g;
        long ibase = (((long)((b << 6) + o0)) << 12) + (y << 6) + x;
#pragma unroll
        for (int px = 0; px < 4; ++px) {
            float I0, I1; unpack2(acc[g * 4 + px], I0, I1);
            long i0 = ibase + px, i1 = i0 + 4096;
            float va, vb;
            if (t) {
                float vp0 = g_vm1[i0], vp1 = g_vm1[i1];
                va = vp0 * (vp0 > 0.5f ? 0.f : DECAYF) + I0;
                vb = vp1 * (vp1 > 0.5f ? 0.f : DECAYF) + I1;
            } else { va = I0; vb = I1; }
            g_vm1[i0] = va; g_vm1[i1] = vb;
            unsigned sa = va > 0.5f ? 1u : 0u;
            unsigned sb = vb > 0.5f ? 1u : 0u;
            int xp = px >> 1;
            pool |= (sa << (4 * g + xp));        // ol=2g   -> bit (2g)*2+xp
            pool |= (sb << (4 * g + 2 + xp));    // ol=2g+1 -> bit (2g+1)*2+xp
        }
    }
    pool |= __shfl_xor_sync(0xffffffffu, pool, 1);   // row partner (y ^ 1)
    if ((row & 1) == 0) {
        int py = y >> 1, pxb = x >> 1;
#pragma unroll
        for (int ol = 0; ol < 8; ++ol) {
            int o = oh * 32 + (pg << 3) + ol;
            int base = (o << 10) + (py << 5) + pxb;
#pragma unroll
            for (int xp = 0; xp < 2; ++xp)
                g_flatT[((base + xp) << 4) + b] =
                    (float)((pool >> (ol * 2 + xp)) & 1u);
        }
    }
}

// ---------------------------------------------------------------------------
// dense0 partials: out[b][j] = sum_i flat[b][i] * D0[j][i].
// grid = 8 j-tiles(64) x 64 i-splits(1024) = 512 blocks, 256 thr.
// ---------------------------------------------------------------------------
__global__ void __launch_bounds__(256) k_dense0(const float* __restrict__ D0)
{
    extern __shared__ float sh[];                        // 64 KB
    unsigned long long* sb2 = (unsigned long long*)sh;   // [p=8][i=1024]
    int jt = blockIdx.x & 7;
    int is = blockIdx.x >> 3;
    int tid = threadIdx.x;
    int jq = tid >> 4, ig = tid & 15;
    int j0 = (jt << 6) + (jq << 2);

    {   // stage flat chunk: [1024 i][16 b] -> pair-major [8 p][1024 i]
        const uint2* src = (const uint2*)(g_flatT + ((long)is << 14));
        uint2* dst = (uint2*)sb2;
        for (int n = tid; n < 8192; n += 256) {
            int i = n >> 3, p = n & 7;
            dst[p * 1024 + i] = src[n];
        }
    }
    __syncthreads();

    unsigned long long acc[32];
#pragma unroll
    for (int q = 0; q < 32; q++) acc[q] = 0ull;

    const float4* dbase4 = (const float4*)(D0 + ((long)j0 << 16) + (is << 10));
#pragma unroll 2
    for (int n = 0; n < 16; ++n) {
        int i4 = ig + (n << 4);                 // float4 column index
        float4 a0 = dbase4[i4];
        float4 a1 = dbase4[16384 + i4];
        float4 a2 = dbase4[32768 + i4];
        float4 a3 = dbase4[49152 + i4];
        float r0[4] = {a0.x, a0.y, a0.z, a0.w};
        float r1[4] = {a1.x, a1.y, a1.z, a1.w};
        float r2[4] = {a2.x, a2.y, a2.z, a2.w};
        float r3[4] = {a3.x, a3.y, a3.z, a3.w};
        int ib = i4 << 2;
#pragma unroll
        for (int k = 0; k < 4; ++k) {
            unsigned long long dd0 = pack2(r0[k], r0[k]);
            unsigned long long dd1 = pack2(r1[k], r1[k]);
            unsigned long long dd2 = pack2(r2[k], r2[k]);
            unsigned long long dd3 = pack2(r3[k], r3[k]);
#pragma unroll
            for (int p = 0; p < 8; ++p) {
                unsigned long long s = sb2[(p << 10) + ib + k];
                FMA2(acc[p],      dd0, s);
                FMA2(acc[8 + p],  dd1, s);
                FMA2(acc[16 + p], dd2, s);
                FMA2(acc[24 + p], dd3, s);
            }
        }
    }
#pragma unroll
    for (int off = 8; off; off >>= 1)
#pragma unroll
        for (int q = 0; q < 32; q++) {
            unsigned long long v = __shfl_xor_sync(0xffffffffu, acc[q], off);
            ADD2(acc[q], v);
        }
    if (ig == 0) {
#pragma unroll
        for (int q = 0; q < 4; q++) {
            float* dst = g_part + (((is << 9) + j0 + q) << 4);
#pragma unroll
            for (int p = 0; p < 8; p++) {
                float a0, a1; unpack2(acc[q * 8 + p], a0, a1);
                dst[2 * p] = a0; dst[2 * p + 1] = a1;
            }
        }
    }
}

// ---------------------------------------------------------------------------
// lif2: reduce 64 partials per (j,b) with 4 lanes each + quad butterfly.
// ---------------------------------------------------------------------------
__global__ void __launch_bounds__(256) k_lif2(int t)
{
    int e = blockIdx.x * 256 + threadIdx.x;
    int r = e & 3;
    int pair = e >> 2;            // 0..8191
    int j = pair >> 4, b = pair & 15;
    float I = 0.f;
#pragma unroll
    for (int k = 0; k < 16; k++)
        I += g_part[((r + 4 * k) << 13) + (j << 4) + b];
    I += __shfl_xor_sync(0xffffffffu, I, 1);
    I += __shfl_xor_sync(0xffffffffu, I, 2);
    if (r == 0) {
        int idx = (b << 9) + j;
        float vm;
        if (t) {
            float vp = g_vm2[idx];
            vm = vp * (vp > 0.5f ? 0.f : DECAYF) + I;
        } else vm = I;
        g_vm2[idx] = vm;
        g_s2f[idx] = vm > 0.5f ? 1.f : 0.f;
    }
}

// ---------------------------------------------------------------------------
// dense1 + LIF3 + accumulate. 1 block, 512 thr; warp w = batch b.
// ---------------------------------------------------------------------------
__global__ void __launch_bounds__(512) k_dense1(const float* __restrict__ D1,
                                                float* __restrict__ out, int t)
{
    int tid = threadIdx.x;
    int b = tid >> 5, lane = tid & 31;
    float s[16];
#pragma unroll
    for (int u = 0; u < 16; u++) s[u] = g_s2f[(b << 9) + lane + (u << 5)];
    float mine = 0.f;
#pragma unroll
    for (int k = 0; k < 11; k++) {
        float acc = 0.f;
#pragma unroll
        for (int u = 0; u < 16; u++)
            acc = fmaf(s[u], D1[(k << 9) + lane + (u << 5)], acc);
#pragma unroll
        for (int off = 16; off; off >>= 1)
            acc += __shfl_xor_sync(0xffffffffu, acc, off);
        if (lane == k) mine = acc;
    }
    if (lane < 11) {
        int idx = b * 11 + lane;
        float vm;
        if (t) {
            float vp = g_vm3[idx];
            vm = vp * (vp > 0.5f ? 0.f : DECAYF) + mine;
        } else vm = mine;
        float sp = vm > 0.5f ? 1.f : 0.f;
        g_vm3[idx] = vm;
        float a = (t ? g_acc[idx] : 0.f) + sp;
        g_acc[idx] = a;
        if (t == 15) out[idx] = a * 0.0625f;
    }
}

// ---------------------------------------------------------------------------
extern "C" void kernel_launch(void* const* d_in, const int* in_sizes, int n_in,
                              void* d_out, int out_size)
{
    (void)in_sizes; (void)n_in; (void)out_size;
    const float* input = (const float*)d_in[0];
    const float* W0    = (const float*)d_in[1];
    const float* W1    = (const float*)d_in[2];
    const float* D0    = (const float*)d_in[3];
    const float* D1    = (const float*)d_in[4];
    float* out = (float*)d_out;

    cudaFuncSetAttribute(k_conv1,  cudaFuncAttributeMaxDynamicSharedMemorySize, 48384);
    cudaFuncSetAttribute(k_dense0, cudaFuncAttributeMaxDynamicSharedMemorySize, 65536);

    // one alignment no-op so the ncu-captured launch (#3, 0-based) is
    // k_dense0 at t=0
    k_nop<<<1, 32>>>();

    for (int t = 0; t < 16; t++) {
        k_conv0 <<<512, 256>>>(input, W0, t);
        k_conv1 <<<512, 256, 48384>>>(W1, t);
        k_dense0<<<512, 256, 65536>>>(D0);
        k_lif2  <<<128, 256>>>(t);
        k_dense1<<<1, 512>>>(D1, out, t);
    }
}

// round 7
// speedup vs baseline: 1.1670x; 1.1670x over previous
#include <cuda_runtime.h>

#define DECAYF 0.951229424500714f   // exp(-1/20)

// Persistent state (no allocs allowed)
__device__ float g_vm0[2097152];      // [16 b][32 o][64][64]
__device__ float g_s0f[2097152];
__device__ float g_vm1[4194304];      // [16 b][64 o][64][64]
__device__ float g_flatT[1048576];    // pooled spikes [i=65536][b=16]
__device__ float g_part[524288];      // dense0 partials [is=64][b=16][j=512]
__device__ float g_vm2[8192];         // [b][j]
__device__ float g_vm3[176], g_acc[176];
__device__ float g_nop[32];

// ---- packed f32x2 helpers ----
__device__ __forceinline__ unsigned long long pack2(float a, float b) {
    unsigned long long r;
    asm("mov.b64 %0, {%1, %2};" : "=l"(r)
        : "r"(__float_as_uint(a)), "r"(__float_as_uint(b)));
    return r;
}
__device__ __forceinline__ void unpack2(unsigned long long v, float& a, float& b) {
    unsigned lo, hi;
    asm("mov.b64 {%0, %1}, %2;" : "=r"(lo), "=r"(hi) : "l"(v));
    a = __uint_as_float(lo); b = __uint_as_float(hi);
}
#define FMA2(acc, w, s) asm("fma.rn.f32x2 %0, %1, %2, %0;" : "+l"(acc) : "l"(w), "l"(s))
#define ADD2(acc, v)    asm("add.rn.f32x2 %0, %0, %1;"      : "+l"(acc) : "l"(v))

// dummy kernel: aligns the ncu-captured launch (#3) onto k_dense0(t=0)
__global__ void k_nop() { g_nop[threadIdx.x] = 0.f; }

// ---------------------------------------------------------------------------
// conv0 (2->32, 3x3 pad1) + LIF0.  grid = 16 b * 32 o = 512 blocks, 256 thr.
// ---------------------------------------------------------------------------
__global__ void __launch_bounds__(256) k_conv0(const float* __restrict__ in,
                                               const float* __restrict__ W0, int t)
{
    int bid = blockIdx.x;
    int o = bid & 31, b = bid >> 5;
    float w[18];
#pragma unroll
    for (int i = 0; i < 18; i++) w[i] = W0[o * 18 + i];
    const float* x0 = in + (((long)(b * 16 + t)) << 13);

#pragma unroll 4
    for (int p = threadIdx.x; p < 4096; p += 256) {
        int y = p >> 6, x = p & 63;
        float acc = 0.f;
#pragma unroll
        for (int c = 0; c < 2; c++)
#pragma unroll
            for (int ky = 0; ky < 3; ky++) {
                int yy = y + ky - 1;
                if ((unsigned)yy < 64u)
#pragma unroll
                    for (int kx = 0; kx < 3; kx++) {
                        int xx = x + kx - 1;
                        if ((unsigned)xx < 64u) {
                            float v = x0[(c << 12) + (yy << 6) + xx];
                            v = fminf(fmaxf(v, 0.f), 1.f);
                            acc = fmaf(w[c * 9 + ky * 3 + kx], v, acc);
                        }
                    }
            }
        long idx = (((long)bid) << 12) + p;
        float vm;
        if (t) {
            float vp = g_vm0[idx];
            vm = vp * (vp > 0.5f ? 0.f : DECAYF) + acc;
        } else vm = acc;
        g_vm0[idx] = vm;
        g_s0f[idx] = vm > 0.5f ? 1.f : 0.f;
    }
}

// ---------------------------------------------------------------------------
// conv1 (32->64, 3x3) + LIF1 + fused 2x2 maxpool (binary OR) -> g_flatT.
// grid = 16 b * 16 tiles(16x16) * 2 och-halves = 512 blocks, 256 threads.
// Thread: 4 och-pairs x 4 px = 16 f32x2 accumulators.
// __launch_bounds__(256,2): cap 128 regs so ptxas can software-pipeline the
// LDS->FMA2 chains (2 blocks/SM fits 78336B smem anyway).
// ---------------------------------------------------------------------------
__global__ void __launch_bounds__(256, 2) k_conv1(const float* __restrict__ W1, int t)
{
    extern __shared__ unsigned char sh1[];
    unsigned long long* wsm = (unsigned long long*)sh1;   // [ck=288][pair=16]
    float* ssm = (float*)(sh1 + 36864);                   // [c=32][18][18]

    int bid  = blockIdx.x;
    int oh   = bid & 1;
    int tile = (bid >> 1) & 15;
    int b    = bid >> 5;
    int ty0  = (tile >> 2) << 4, tx0 = (tile & 3) << 4;
    int tid  = threadIdx.x;
    int pg   = tid >> 6;          // 0..3 : pair group (4 pairs = 8 och)
    int pxg  = tid & 63;
    int row  = pxg & 15;
    int px0  = (pxg >> 4) << 2;   // 0,4,8,12

    // weights: pair (o, o+1), o = oh*32 + 2*pr
    for (int idx = tid; idx < 4608; idx += 256) {
        int ck = idx >> 4, pr = idx & 15;
        const float* wb = W1 + (oh * 32 + 2 * pr) * 288 + ck;
        wsm[ck * 16 + pr] = pack2(wb[0], wb[288]);
    }
    // f32 spike halo (zero padded)
    for (int idx = tid; idx < 10368; idx += 256) {
        int c = idx / 324, r = idx - c * 324;
        int yy = r / 18, xx = r - yy * 18;
        int y = ty0 - 1 + yy, x = tx0 - 1 + xx;
        float v = 0.f;
        if ((unsigned)y < 64u && (unsigned)x < 64u)
            v = g_s0f[(((b << 5) + c) << 12) + (y << 6) + x];
        ssm[idx] = v;
    }
    __syncthreads();

    unsigned long long acc[16];
#pragma unroll
    for (int i = 0; i < 16; i++) acc[i] = 0ull;

    for (int c = 0; c < 32; ++c) {
#pragma unroll
        for (int ky = 0; ky < 3; ++ky) {
            const float* rp = ssm + c * 324 + (row + ky) * 18 + px0;
            unsigned long long s2[6];
#pragma unroll
            for (int u = 0; u < 6; ++u) {
                float s = rp[u];
                s2[u] = pack2(s, s);
            }
#pragma unroll
            for (int kx = 0; kx < 3; ++kx) {
                const ulonglong2* wp =
                    (const ulonglong2*)(wsm + (c * 9 + ky * 3 + kx) * 16 + (pg << 2));
                ulonglong2 wa = wp[0], wb = wp[1];
                unsigned long long wv[4] = {wa.x, wa.y, wb.x, wb.y};
#pragma unroll
                for (int g = 0; g < 4; ++g)
#pragma unroll
                    for (int px = 0; px < 4; ++px)
                        FMA2(acc[g * 4 + px], wv[g], s2[kx + px]);
            }
        }
    }

    // LIF1 + pooled bits.  bit index = ol*2 + xp  (ol = channel 0..7).
    int y = ty0 + row, x = tx0 + px0;
    unsigned pool = 0u;
#pragma unroll
    for (int g = 0; g < 4; ++g) {
        int o0 = oh * 32 + (pg << 3) + 2 * g;
        long ibase = (((long)((b << 6) + o0)) << 12) + (y << 6) + x;
#pragma unroll
        for (int px = 0; px < 4; ++px) {
            float I0, I1; unpack2(acc[g * 4 + px], I0, I1);
            long i0 = ibase + px, i1 = i0 + 4096;
            float va, vb;
            if (t) {
                float vp0 = g_vm1[i0], vp1 = g_vm1[i1];
                va = vp0 * (vp0 > 0.5f ? 0.f : DECAYF) + I0;
                vb = vp1 * (vp1 > 0.5f ? 0.f : DECAYF) + I1;
            } else { va = I0; vb = I1; }
            g_vm1[i0] = va; g_vm1[i1] = vb;
            unsigned sa = va > 0.5f ? 1u : 0u;
            unsigned sb = vb > 0.5f ? 1u : 0u;
            int xp = px >> 1;
            pool |= (sa << (4 * g + xp));        // ol=2g   -> bit (2g)*2+xp
            pool |= (sb << (4 * g + 2 + xp));    // ol=2g+1 -> bit (2g+1)*2+xp
        }
    }
    pool |= __shfl_xor_sync(0xffffffffu, pool, 1);   // row partner (y ^ 1)
    if ((row & 1) == 0) {
        int py = y >> 1, pxb = x >> 1;
#pragma unroll
        for (int ol = 0; ol < 8; ++ol) {
            int o = oh * 32 + (pg << 3) + ol;
            int base = (o << 10) + (py << 5) + pxb;
#pragma unroll
            for (int xp = 0; xp < 2; ++xp)
                g_flatT[((base + xp) << 4) + b] =
                    (float)((pool >> (ol * 2 + xp)) & 1u);
        }
    }
}

// ---------------------------------------------------------------------------
// dense0 partials: out[b][j] = sum_i flat[b][i] * D0[j][i].
// grid = 8 j-tiles(64) x 64 i-splits(1024) = 512 blocks, 256 thr.
// Spike smem k-interleaved: logical pair (p, i) at physical
//   (p<<10) + ((i&3)<<8) + (i>>2)  -> FMA reads (p<<10)+(k<<8)+i4 with lanes'
//   i4 consecutive = conflict-free LDS.64 while D0 uses LDG.128 (float4).
// Output written transposed: g_part[is][b][j] for the fused tail.
// ---------------------------------------------------------------------------
__global__ void __launch_bounds__(256, 2) k_dense0(const float* __restrict__ D0)
{
    extern __shared__ float sh[];                        // 64 KB
    unsigned long long* sb2 = (unsigned long long*)sh;   // physical layout above
    int jt = blockIdx.x & 7;
    int is = blockIdx.x >> 3;
    int tid = threadIdx.x;
    int jq = tid >> 4, ig = tid & 15;
    int j0 = (jt << 6) + (jq << 2);

    {   // stage flat chunk: [1024 i][16 b] -> k-interleaved pair-major
        const uint2* src = (const uint2*)(g_flatT + ((long)is << 14));
        uint2* dst = (uint2*)sb2;
        for (int n = tid; n < 8192; n += 256) {
            int i = n >> 3, p = n & 7;
            dst[(p << 10) + ((i & 3) << 8) + (i >> 2)] = src[n];
        }
    }
    __syncthreads();

    unsigned long long acc[32];
#pragma unroll
    for (int q = 0; q < 32; q++) acc[q] = 0ull;

    const float4* dbase4 = (const float4*)(D0 + ((long)j0 << 16) + (is << 10));
#pragma unroll 2
    for (int n = 0; n < 16; ++n) {
        int i4 = ig + (n << 4);                 // float4 column index
        float4 a0 = dbase4[i4];
        float4 a1 = dbase4[16384 + i4];
        float4 a2 = dbase4[32768 + i4];
        float4 a3 = dbase4[49152 + i4];
        float r0[4] = {a0.x, a0.y, a0.z, a0.w};
        float r1[4] = {a1.x, a1.y, a1.z, a1.w};
        float r2[4] = {a2.x, a2.y, a2.z, a2.w};
        float r3[4] = {a3.x, a3.y, a3.z, a3.w};
#pragma unroll
        for (int k = 0; k < 4; ++k) {
            unsigned long long dd0 = pack2(r0[k], r0[k]);
            unsigned long long dd1 = pack2(r1[k], r1[k]);
            unsigned long long dd2 = pack2(r2[k], r2[k]);
            unsigned long long dd3 = pack2(r3[k], r3[k]);
#pragma unroll
            for (int p = 0; p < 8; ++p) {
                unsigned long long s = sb2[(p << 10) + (k << 8) + i4];
                FMA2(acc[p],      dd0, s);
                FMA2(acc[8 + p],  dd1, s);
                FMA2(acc[16 + p], dd2, s);
                FMA2(acc[24 + p], dd3, s);
            }
        }
    }
#pragma unroll
    for (int off = 8; off; off >>= 1)
#pragma unroll
        for (int q = 0; q < 32; q++) {
            unsigned long long v = __shfl_xor_sync(0xffffffffu, acc[q], off);
            ADD2(acc[q], v);
        }
    if (ig == 0) {
        // g_part layout: [is][b][j]
#pragma unroll
        for (int q = 0; q < 4; q++) {
            int j = j0 + q;
#pragma unroll
            for (int p = 0; p < 8; p++) {
                float a0, a1; unpack2(acc[q * 8 + p], a0, a1);
                g_part[(is << 13) + ((2 * p)     << 9) + j] = a0;
                g_part[(is << 13) + ((2 * p + 1) << 9) + j] = a1;
            }
        }
    }
}

// ---------------------------------------------------------------------------
// fused tail: per-batch block. lif2 reduce (coalesced over j) + dense1 + LIF3.
// grid = 16 (batch), 512 threads.
// ---------------------------------------------------------------------------
__global__ void __launch_bounds__(512) k_tail2(const float* __restrict__ D1,
                                               float* __restrict__ out, int t)
{
    __shared__ float s2[512];
    int b = blockIdx.x;
    int tid = threadIdx.x;     // = j
    float I = 0.f;
#pragma unroll 8
    for (int is = 0; is < 64; is++)
        I += g_part[(is << 13) + (b << 9) + tid];
    int idx = (b << 9) + tid;
    float vm;
    if (t) {
        float vp = g_vm2[idx];
        vm = vp * (vp > 0.5f ? 0.f : DECAYF) + I;
    } else vm = I;
    g_vm2[idx] = vm;
    s2[tid] = vm > 0.5f ? 1.f : 0.f;
    __syncthreads();

    int w = tid >> 5, lane = tid & 31;
    if (w < 11) {
        float acc = 0.f;
#pragma unroll
        for (int u = 0; u < 16; u++)
            acc = fmaf(s2[lane + (u << 5)], D1[(w << 9) + lane + (u << 5)], acc);
#pragma unroll
        for (int off = 16; off; off >>= 1)
            acc += __shfl_xor_sync(0xffffffffu, acc, off);
        if (lane == 0) {
            int oidx = b * 11 + w;
            float vm3;
            if (t) {
                float vp = g_vm3[oidx];
                vm3 = vp * (vp > 0.5f ? 0.f : DECAYF) + acc;
            } else vm3 = acc;
            float sp = vm3 > 0.5f ? 1.f : 0.f;
            g_vm3[oidx] = vm3;
            float a = (t ? g_acc[oidx] : 0.f) + sp;
            g_acc[oidx] = a;
            if (t == 15) out[oidx] = a * 0.0625f;
        }
    }
}

// ---------------------------------------------------------------------------
extern "C" void kernel_launch(void* const* d_in, const int* in_sizes, int n_in,
                              void* d_out, int out_size)
{
    (void)in_sizes; (void)n_in; (void)out_size;
    const float* input = (const float*)d_in[0];
    const float* W0    = (const float*)d_in[1];
    const float* W1    = (const float*)d_in[2];
    const float* D0    = (const float*)d_in[3];
    const float* D1    = (const float*)d_in[4];
    float* out = (float*)d_out;

    cudaFuncSetAttribute(k_conv1,  cudaFuncAttributeMaxDynamicSharedMemorySize, 78336);
    cudaFuncSetAttribute(k_dense0, cudaFuncAttributeMaxDynamicSharedMemorySize, 65536);

    // alignment no-op: ncu-captured launch (#3, 0-based) = k_dense0 at t=0
    k_nop<<<1, 32>>>();

    for (int t = 0; t < 16; t++) {
        k_conv0 <<<512, 256>>>(input, W0, t);
        k_conv1 <<<512, 256, 78336>>>(W1, t);
        k_dense0<<<512, 256, 65536>>>(D0);
        k_tail2 <<<16, 512>>>(D1, out, t);
    }
}